// round 16
// baseline (speedup 1.0000x reference)
#include <cuda_runtime.h>
#include <cuda_bf16.h>
#include <cstdint>

#define HID        256
#define COLS       32                 // hid chunk per CTA (floats) -> 128 B per row
#define CGV        (COLS / 4)         // 8 float4 groups per row
#define THREADS    512
#define STRIPS     (THREADS / CGV)    // 64 row strips
#define ROWS_MAX   512
#define RPT        (ROWS_MAX / STRIPS) // 8 rows per thread
#define RPT_H      (RPT / 2)           // 4 rows per pipeline stage
#define NGRAPH_MAX 1024
#define EPS_F      1e-6f
#define NWARPS     (THREADS / 32)     // 16

__device__ int d_offsets[NGRAPH_MAX + 1];

// Warp-shuffle scan of batch_list -> exclusive offsets; signals dependents (PDL).
__global__ void prefix_kernel(const int* __restrict__ batch, int B) {
    __shared__ int wsum[32];
    int t = threadIdx.x;
    int lane = t & 31, w = t >> 5;
    int v = (t < B) ? batch[t] : 0;
#pragma unroll
    for (int d = 1; d < 32; d <<= 1) {
        int n = __shfl_up_sync(0xFFFFFFFFu, v, d);
        if (lane >= d) v += n;
    }
    if (lane == 31) wsum[w] = v;
    __syncthreads();
    if (w == 0) {
        int x = wsum[lane];
#pragma unroll
        for (int d = 1; d < 32; d <<= 1) {
            int n = __shfl_up_sync(0xFFFFFFFFu, x, d);
            if (lane >= d) x += n;
        }
        wsum[lane] = x;
    }
    __syncthreads();
    int add = (w > 0) ? wsum[w - 1] : 0;
    v += add;
    d_offsets[t + 1] = v;
    if (t == 0) d_offsets[0] = 0;
    __syncthreads();   // all d_offsets writes done before signaling dependents
    asm volatile("griddepcontrol.launch_dependents;" ::: "memory");
}

__device__ __forceinline__ void cp_async16(uint32_t smem_addr, const void* gptr) {
    asm volatile("cp.async.cg.shared.global [%0], [%1], 16;\n"
                 :: "r"(smem_addr), "l"(gptr) : "memory");
}

__device__ __forceinline__ void acc4(const float4 v, float4& s, float4& q) {
    s.x += v.x; s.y += v.y; s.z += v.z; s.w += v.w;
    q.x = fmaf(v.x, v.x, q.x);
    q.y = fmaf(v.y, v.y, q.y);
    q.z = fmaf(v.z, v.z, q.z);
    q.w = fmaf(v.w, v.w, q.w);
}

__global__ __launch_bounds__(THREADS, 3)
void graphnorm_kernel(const float* __restrict__ x,
                      const float* __restrict__ weight,
                      const float* __restrict__ bias,
                      const float* __restrict__ mscale,
                      float*       __restrict__ out)
{
    extern __shared__ float smem[];
    float* tile = smem;                                  // 512*32 floats = 64 KB
    float4* sh_ws = reinterpret_cast<float4*>(tile + ROWS_MAX * COLS);        // [NWARPS][CGV]
    float4* sh_wq = sh_ws + NWARPS * CGV;                                     // [NWARPS][CGV]
    float4* sh_a  = sh_wq + NWARPS * CGV;                                     // [CGV]
    float4* sh_b  = sh_a + CGV;                                               // [CGV]
    float4* sh_w  = sh_b + CGV;                                               // [CGV]
    float4* sh_bi = sh_w + CGV;                                               // [CGV]
    float4* sh_ms = sh_bi + CGV;                                              // [CGV]

    const int tid   = threadIdx.x;
    const int cg    = tid & (CGV - 1);             // float4 column group 0..7
    const int strip = tid >> 3;                    // row strip 0..63
    const int lane  = tid & 31;
    const int warp  = tid >> 5;
    const int g     = blockIdx.y;                  // graph
    const int hc    = blockIdx.x;                  // hid chunk (0..7)
    const int r0    = strip * RPT;

    // ---- Work independent of d_offsets: param prefetch + address setup.
    //      Runs in the PDL shadow while prefix_kernel finishes. ----
    if (warp == NWARPS - 1 && lane < CGV) {
        const int c4 = hc * CGV + lane;
        sh_w[lane]  = __ldg(&reinterpret_cast<const float4*>(weight)[c4]);
        sh_bi[lane] = __ldg(&reinterpret_cast<const float4*>(bias)[c4]);
        sh_ms[lane] = __ldg(&reinterpret_cast<const float4*>(mscale)[c4]);
    }
    uint32_t smem_row = __cvta_generic_to_shared(tile + (size_t)r0 * COLS + cg * 4);
    const float4* trow = reinterpret_cast<const float4*>(tile) + (size_t)r0 * CGV + cg;

    // ---- Wait for prefix kernel's d_offsets writes (PDL edge). ----
    asm volatile("griddepcontrol.wait;" ::: "memory");

    const int offset = d_offsets[g];
    const int count  = d_offsets[g + 1] - offset;

    const float* gbase = x + (size_t)offset * HID + hc * COLS + cg * 4;
    float*       obase = out + (size_t)offset * HID + hc * COLS + cg * 4;

    // ---- Stage tile into smem in 2 pipelined groups (self-consumed) ----
#pragma unroll
    for (int i = 0; i < RPT_H; i++) {
        int r = r0 + i;
        if (r < count)
            cp_async16(smem_row + (uint32_t)i * (COLS * 4),
                       gbase + (size_t)r * HID);
    }
    asm volatile("cp.async.commit_group;\n" ::: "memory");
#pragma unroll
    for (int i = RPT_H; i < RPT; i++) {
        int r = r0 + i;
        if (r < count)
            cp_async16(smem_row + (uint32_t)i * (COLS * 4),
                       gbase + (size_t)r * HID);
    }
    asm volatile("cp.async.commit_group;\n" ::: "memory");

    float4 s = make_float4(0.f, 0.f, 0.f, 0.f);
    float4 q = make_float4(0.f, 0.f, 0.f, 0.f);

    asm volatile("cp.async.wait_group 1;\n" ::: "memory");   // group A landed
#pragma unroll
    for (int i = 0; i < RPT_H; i++) {
        int r = r0 + i;
        if (r < count) acc4(trow[(size_t)i * CGV], s, q);
    }
    asm volatile("cp.async.wait_group 0;\n" ::: "memory");   // group B landed
#pragma unroll
    for (int i = RPT_H; i < RPT; i++) {
        int r = r0 + i;
        if (r < count) acc4(trow[(size_t)i * CGV], s, q);
    }

    // In-warp reduce: lanes l, l+8, l+16, l+24 share the same cg.
#pragma unroll
    for (int d = 16; d >= 8; d >>= 1) {
        s.x += __shfl_down_sync(0xFFFFFFFFu, s.x, d);
        s.y += __shfl_down_sync(0xFFFFFFFFu, s.y, d);
        s.z += __shfl_down_sync(0xFFFFFFFFu, s.z, d);
        s.w += __shfl_down_sync(0xFFFFFFFFu, s.w, d);
        q.x += __shfl_down_sync(0xFFFFFFFFu, q.x, d);
        q.y += __shfl_down_sync(0xFFFFFFFFu, q.y, d);
        q.z += __shfl_down_sync(0xFFFFFFFFu, q.z, d);
        q.w += __shfl_down_sync(0xFFFFFFFFu, q.w, d);
    }
    if (lane < CGV) {
        sh_ws[warp * CGV + lane] = s;
        sh_wq[warp * CGV + lane] = q;
    }
    __syncthreads();

    // ---- Final reduce spread over warp 0 (4 threads per column group) ----
    if (warp == 0) {
        const int c    = lane & (CGV - 1);   // column group 0..7
        const int part = lane >> 3;          // partial quarter 0..3
        float4 S = make_float4(0.f, 0.f, 0.f, 0.f);
        float4 Q = make_float4(0.f, 0.f, 0.f, 0.f);
#pragma unroll
        for (int w = 0; w < NWARPS / 4; w++) {
            const int widx = part * (NWARPS / 4) + w;
            float4 ps = sh_ws[widx * CGV + c];
            float4 pq = sh_wq[widx * CGV + c];
            S.x += ps.x; S.y += ps.y; S.z += ps.z; S.w += ps.w;
            Q.x += pq.x; Q.y += pq.y; Q.z += pq.z; Q.w += pq.w;
        }
#pragma unroll
        for (int d = 16; d >= 8; d >>= 1) {
            S.x += __shfl_down_sync(0xFFFFFFFFu, S.x, d);
            S.y += __shfl_down_sync(0xFFFFFFFFu, S.y, d);
            S.z += __shfl_down_sync(0xFFFFFFFFu, S.z, d);
            S.w += __shfl_down_sync(0xFFFFFFFFu, S.w, d);
            Q.x += __shfl_down_sync(0xFFFFFFFFu, Q.x, d);
            Q.y += __shfl_down_sync(0xFFFFFFFFu, Q.y, d);
            Q.z += __shfl_down_sync(0xFFFFFFFFu, Q.z, d);
            Q.w += __shfl_down_sync(0xFFFFFFFFu, Q.w, d);
        }
        if (lane < CGV) {
            const float inv = (count > 0) ? (1.f / (float)count) : 0.f;
            const float4 w4  = sh_w[lane];
            const float4 bi4 = sh_bi[lane];
            const float4 ms4 = sh_ms[lane];

            float4 a, bb;
            float mean, msq, var, rstd;
            mean = S.x * inv; msq = Q.x * inv;
            var  = msq - mean * mean * ms4.x * (2.f - ms4.x);
            rstd = rsqrtf(var + EPS_F);
            a.x  = w4.x * rstd;  bb.x = bi4.x - a.x * mean * ms4.x;

            mean = S.y * inv; msq = Q.y * inv;
            var  = msq - mean * mean * ms4.y * (2.f - ms4.y);
            rstd = rsqrtf(var + EPS_F);
            a.y  = w4.y * rstd;  bb.y = bi4.y - a.y * mean * ms4.y;

            mean = S.z * inv; msq = Q.z * inv;
            var  = msq - mean * mean * ms4.z * (2.f - ms4.z);
            rstd = rsqrtf(var + EPS_F);
            a.z  = w4.z * rstd;  bb.z = bi4.z - a.z * mean * ms4.z;

            mean = S.w * inv; msq = Q.w * inv;
            var  = msq - mean * mean * ms4.w * (2.f - ms4.w);
            rstd = rsqrtf(var + EPS_F);
            a.w  = w4.w * rstd;  bb.w = bi4.w - a.w * mean * ms4.w;

            sh_a[lane] = a;
            sh_b[lane] = bb;
        }
    }
    __syncthreads();

    // ---- Normalize from smem (self-written rows), write gmem once ----
    const float4 a  = sh_a[cg];
    const float4 bb = sh_b[cg];
#pragma unroll
    for (int i = 0; i < RPT; i++) {
        int r = r0 + i;
        if (r < count) {
            float4 v = trow[(size_t)i * CGV];
            float4 o;
            o.x = fmaf(a.x, v.x, bb.x);
            o.y = fmaf(a.y, v.y, bb.y);
            o.z = fmaf(a.z, v.z, bb.z);
            o.w = fmaf(a.w, v.w, bb.w);
            *reinterpret_cast<float4*>(obase + (size_t)r * HID) = o;
        }
    }
}

extern "C" void kernel_launch(void* const* d_in, const int* in_sizes, int n_in,
                              void* d_out, int out_size) {
    const float* tensor = (const float*)d_in[0];
    const int*   batch  = (const int*)d_in[1];
    const float* weight = (const float*)d_in[2];
    const float* bias   = (const float*)d_in[3];
    const float* mscale = (const float*)d_in[4];
    float*       out    = (float*)d_out;

    const int B = in_sizes[1];

    const int smem_bytes = ROWS_MAX * COLS * sizeof(float)
                         + 2 * NWARPS * CGV * sizeof(float4)
                         + 5 * CGV * sizeof(float4);
    static bool attr_set = false;
    if (!attr_set) {
        cudaFuncSetAttribute(graphnorm_kernel,
                             cudaFuncAttributeMaxDynamicSharedMemorySize, smem_bytes);
        attr_set = true;
    }

    prefix_kernel<<<1, NGRAPH_MAX>>>(batch, B);

    cudaLaunchConfig_t cfg = {};
    cfg.gridDim  = dim3(HID / COLS, (unsigned)B, 1);
    cfg.blockDim = dim3(THREADS, 1, 1);
    cfg.dynamicSmemBytes = smem_bytes;
    cudaLaunchAttribute attrs[1];
    attrs[0].id = cudaLaunchAttributeProgrammaticStreamSerialization;
    attrs[0].val.programmaticStreamSerializationAllowed = 1;
    cfg.attrs = attrs;
    cfg.numAttrs = 1;
    cudaLaunchKernelEx(&cfg, graphnorm_kernel, tensor, weight, bias, mscale, out);
}

// round 17
// speedup vs baseline: 1.0026x; 1.0026x over previous
#include <cuda_runtime.h>
#include <cuda_bf16.h>
#include <cstdint>

#define HID        256
#define COLS       32                 // hid chunk per CTA (floats) -> 128 B per row
#define CGV        (COLS / 4)         // 8 float4 groups per row
#define THREADS    512
#define STRIPS     (THREADS / CGV)    // 64 row strips
#define ROWS_MAX   512
#define RPT        (ROWS_MAX / STRIPS) // 8 rows per thread
#define RPT_H      (RPT / 2)           // 4 rows per pipeline stage
#define NGRAPH_MAX 1024
#define EPS_F      1e-6f
#define NWARPS     (THREADS / 32)     // 16

__device__ int d_offsets[NGRAPH_MAX + 1];

// Warp-shuffle scan of batch_list -> exclusive offsets; signals dependents (PDL).
__global__ void prefix_kernel(const int* __restrict__ batch, int B) {
    __shared__ int wsum[32];
    int t = threadIdx.x;
    int lane = t & 31, w = t >> 5;
    int v = (t < B) ? batch[t] : 0;
#pragma unroll
    for (int d = 1; d < 32; d <<= 1) {
        int n = __shfl_up_sync(0xFFFFFFFFu, v, d);
        if (lane >= d) v += n;
    }
    if (lane == 31) wsum[w] = v;
    __syncthreads();
    if (w == 0) {
        int x = wsum[lane];
#pragma unroll
        for (int d = 1; d < 32; d <<= 1) {
            int n = __shfl_up_sync(0xFFFFFFFFu, x, d);
            if (lane >= d) x += n;
        }
        wsum[lane] = x;
    }
    __syncthreads();
    int add = (w > 0) ? wsum[w - 1] : 0;
    v += add;
    d_offsets[t + 1] = v;
    if (t == 0) d_offsets[0] = 0;
    __syncthreads();   // all d_offsets writes done before signaling dependents
    asm volatile("griddepcontrol.launch_dependents;" ::: "memory");
}

__device__ __forceinline__ void cp_async16(uint32_t smem_addr, const void* gptr) {
    asm volatile("cp.async.cg.shared.global [%0], [%1], 16;\n"
                 :: "r"(smem_addr), "l"(gptr) : "memory");
}

__device__ __forceinline__ void acc4(const float4 v, float4& s, float4& q) {
    s.x += v.x; s.y += v.y; s.z += v.z; s.w += v.w;
    q.x = fmaf(v.x, v.x, q.x);
    q.y = fmaf(v.y, v.y, q.y);
    q.z = fmaf(v.z, v.z, q.z);
    q.w = fmaf(v.w, v.w, q.w);
}

__global__ __launch_bounds__(THREADS, 3)
void graphnorm_kernel(const float* __restrict__ x,
                      const float* __restrict__ weight,
                      const float* __restrict__ bias,
                      const float* __restrict__ mscale,
                      float*       __restrict__ out)
{
    extern __shared__ float smem[];
    float* tile = smem;                                  // 512*32 floats = 64 KB
    float4* sh_ws = reinterpret_cast<float4*>(tile + ROWS_MAX * COLS);        // [NWARPS][CGV]
    float4* sh_wq = sh_ws + NWARPS * CGV;                                     // [NWARPS][CGV]
    float4* sh_a  = sh_wq + NWARPS * CGV;                                     // [CGV]
    float4* sh_b  = sh_a + CGV;                                               // [CGV]
    float4* sh_w  = sh_b + CGV;                                               // [CGV]
    float4* sh_bi = sh_w + CGV;                                               // [CGV]
    float4* sh_ms = sh_bi + CGV;                                              // [CGV]

    const int tid   = threadIdx.x;
    const int cg    = tid & (CGV - 1);             // float4 column group 0..7
    const int strip = tid >> 3;                    // row strip 0..63
    const int lane  = tid & 31;
    const int warp  = tid >> 5;
    const int g     = blockIdx.y;                  // graph
    const int hc    = blockIdx.x;                  // hid chunk (0..7)

    // Wait for prefix kernel's d_offsets writes (PDL edge).
    asm volatile("griddepcontrol.wait;" ::: "memory");

    const int offset = d_offsets[g];
    const int count  = d_offsets[g + 1] - offset;

    const float* gbase = x + (size_t)offset * HID + hc * COLS + cg * 4;
    float*       obase = out + (size_t)offset * HID + hc * COLS + cg * 4;

    const int r0 = strip * RPT;
    uint32_t smem_row = __cvta_generic_to_shared(tile + (size_t)r0 * COLS + cg * 4);

    // ---- Stage tile into smem in 2 pipelined groups (self-consumed) ----
#pragma unroll
    for (int i = 0; i < RPT_H; i++) {
        int r = r0 + i;
        if (r < count)
            cp_async16(smem_row + (uint32_t)i * (COLS * 4),
                       gbase + (size_t)r * HID);
    }
    asm volatile("cp.async.commit_group;\n" ::: "memory");
#pragma unroll
    for (int i = RPT_H; i < RPT; i++) {
        int r = r0 + i;
        if (r < count)
            cp_async16(smem_row + (uint32_t)i * (COLS * 4),
                       gbase + (size_t)r * HID);
    }
    asm volatile("cp.async.commit_group;\n" ::: "memory");

    // ---- Prefetch per-column params into smem, hidden behind the tile DMA ----
    if (warp == NWARPS - 1 && lane < CGV) {
        const int c4 = hc * CGV + lane;
        sh_w[lane]  = __ldg(&reinterpret_cast<const float4*>(weight)[c4]);
        sh_bi[lane] = __ldg(&reinterpret_cast<const float4*>(bias)[c4]);
        sh_ms[lane] = __ldg(&reinterpret_cast<const float4*>(mscale)[c4]);
    }

    float4 s = make_float4(0.f, 0.f, 0.f, 0.f);
    float4 q = make_float4(0.f, 0.f, 0.f, 0.f);
    const float4* trow = reinterpret_cast<const float4*>(tile) + (size_t)r0 * CGV + cg;

    asm volatile("cp.async.wait_group 1;\n" ::: "memory");   // group A landed
#pragma unroll
    for (int i = 0; i < RPT_H; i++) {
        int r = r0 + i;
        if (r < count) acc4(trow[(size_t)i * CGV], s, q);
    }
    asm volatile("cp.async.wait_group 0;\n" ::: "memory");   // group B landed
#pragma unroll
    for (int i = RPT_H; i < RPT; i++) {
        int r = r0 + i;
        if (r < count) acc4(trow[(size_t)i * CGV], s, q);
    }

    // In-warp reduce: lanes l, l+8, l+16, l+24 share the same cg.
#pragma unroll
    for (int d = 16; d >= 8; d >>= 1) {
        s.x += __shfl_down_sync(0xFFFFFFFFu, s.x, d);
        s.y += __shfl_down_sync(0xFFFFFFFFu, s.y, d);
        s.z += __shfl_down_sync(0xFFFFFFFFu, s.z, d);
        s.w += __shfl_down_sync(0xFFFFFFFFu, s.w, d);
        q.x += __shfl_down_sync(0xFFFFFFFFu, q.x, d);
        q.y += __shfl_down_sync(0xFFFFFFFFu, q.y, d);
        q.z += __shfl_down_sync(0xFFFFFFFFu, q.z, d);
        q.w += __shfl_down_sync(0xFFFFFFFFu, q.w, d);
    }
    if (lane < CGV) {
        sh_ws[warp * CGV + lane] = s;
        sh_wq[warp * CGV + lane] = q;
    }
    __syncthreads();

    // ---- Final reduce spread over warp 0 (4 threads per column group) ----
    if (warp == 0) {
        const int c    = lane & (CGV - 1);   // column group 0..7
        const int part = lane >> 3;          // partial quarter 0..3
        float4 S = make_float4(0.f, 0.f, 0.f, 0.f);
        float4 Q = make_float4(0.f, 0.f, 0.f, 0.f);
#pragma unroll
        for (int w = 0; w < NWARPS / 4; w++) {
            const int widx = part * (NWARPS / 4) + w;
            float4 ps = sh_ws[widx * CGV + c];
            float4 pq = sh_wq[widx * CGV + c];
            S.x += ps.x; S.y += ps.y; S.z += ps.z; S.w += ps.w;
            Q.x += pq.x; Q.y += pq.y; Q.z += pq.z; Q.w += pq.w;
        }
        // combine the 4 quarters: lanes c, c+8, c+16, c+24
#pragma unroll
        for (int d = 16; d >= 8; d >>= 1) {
            S.x += __shfl_down_sync(0xFFFFFFFFu, S.x, d);
            S.y += __shfl_down_sync(0xFFFFFFFFu, S.y, d);
            S.z += __shfl_down_sync(0xFFFFFFFFu, S.z, d);
            S.w += __shfl_down_sync(0xFFFFFFFFu, S.w, d);
            Q.x += __shfl_down_sync(0xFFFFFFFFu, Q.x, d);
            Q.y += __shfl_down_sync(0xFFFFFFFFu, Q.y, d);
            Q.z += __shfl_down_sync(0xFFFFFFFFu, Q.z, d);
            Q.w += __shfl_down_sync(0xFFFFFFFFu, Q.w, d);
        }
        if (lane < CGV) {
            const float inv = (count > 0) ? (1.f / (float)count) : 0.f;
            const float4 w4  = sh_w[lane];
            const float4 bi4 = sh_bi[lane];
            const float4 ms4 = sh_ms[lane];

            float4 a, bb;
            float mean, msq, var, rstd;
            mean = S.x * inv; msq = Q.x * inv;
            var  = msq - mean * mean * ms4.x * (2.f - ms4.x);
            rstd = rsqrtf(var + EPS_F);
            a.x  = w4.x * rstd;  bb.x = bi4.x - a.x * mean * ms4.x;

            mean = S.y * inv; msq = Q.y * inv;
            var  = msq - mean * mean * ms4.y * (2.f - ms4.y);
            rstd = rsqrtf(var + EPS_F);
            a.y  = w4.y * rstd;  bb.y = bi4.y - a.y * mean * ms4.y;

            mean = S.z * inv; msq = Q.z * inv;
            var  = msq - mean * mean * ms4.z * (2.f - ms4.z);
            rstd = rsqrtf(var + EPS_F);
            a.z  = w4.z * rstd;  bb.z = bi4.z - a.z * mean * ms4.z;

            mean = S.w * inv; msq = Q.w * inv;
            var  = msq - mean * mean * ms4.w * (2.f - ms4.w);
            rstd = rsqrtf(var + EPS_F);
            a.w  = w4.w * rstd;  bb.w = bi4.w - a.w * mean * ms4.w;

            sh_a[lane] = a;
            sh_b[lane] = bb;
        }
    }
    __syncthreads();

    // ---- Normalize from smem (self-written rows), write gmem once ----
    const float4 a  = sh_a[cg];
    const float4 bb = sh_b[cg];
#pragma unroll
    for (int i = 0; i < RPT; i++) {
        int r = r0 + i;
        if (r < count) {
            float4 v = trow[(size_t)i * CGV];
            float4 o;
            o.x = fmaf(a.x, v.x, bb.x);
            o.y = fmaf(a.y, v.y, bb.y);
            o.z = fmaf(a.z, v.z, bb.z);
            o.w = fmaf(a.w, v.w, bb.w);
            *reinterpret_cast<float4*>(obase + (size_t)r * HID) = o;
        }
    }
}

extern "C" void kernel_launch(void* const* d_in, const int* in_sizes, int n_in,
                              void* d_out, int out_size) {
    const float* tensor = (const float*)d_in[0];
    const int*   batch  = (const int*)d_in[1];
    const float* weight = (const float*)d_in[2];
    const float* bias   = (const float*)d_in[3];
    const float* mscale = (const float*)d_in[4];
    float*       out    = (float*)d_out;

    const int B = in_sizes[1];

    const int smem_bytes = ROWS_MAX * COLS * sizeof(float)
                         + 2 * NWARPS * CGV * sizeof(float4)
                         + 5 * CGV * sizeof(float4);
    static bool attr_set = false;
    if (!attr_set) {
        cudaFuncSetAttribute(graphnorm_kernel,
                             cudaFuncAttributeMaxDynamicSharedMemorySize, smem_bytes);
        attr_set = true;
    }

    prefix_kernel<<<1, NGRAPH_MAX>>>(batch, B);

    // Main kernel with programmatic dependent launch: overlaps its launch/setup
    // with the prefix kernel; d_offsets reads are fenced by griddepcontrol.wait.
    cudaLaunchConfig_t cfg = {};
    cfg.gridDim  = dim3(HID / COLS, (unsigned)B, 1);
    cfg.blockDim = dim3(THREADS, 1, 1);
    cfg.dynamicSmemBytes = smem_bytes;
    cudaLaunchAttribute attrs[1];
    attrs[0].id = cudaLaunchAttributeProgrammaticStreamSerialization;
    attrs[0].val.programmaticStreamSerializationAllowed = 1;
    cfg.attrs = attrs;
    cfg.numAttrs = 1;
    cudaLaunchKernelEx(&cfg, graphnorm_kernel, tensor, weight, bias, mscale, out);
}